// round 1
// baseline (speedup 1.0000x reference)
#include <cuda_runtime.h>
#include <cuda_bf16.h>
#include <math.h>

// Problem constants (fixed shapes)
#define BB 4
#define TT 128
#define DD 768
#define HH 770
#define LL 40
#define PP (TT*TT)          // 16384 pairs per batch
#define NROWS (BB*TT)       // 512
#define NSPLIT 32
#define PCHUNK (PP/NSPLIT)  // 512

// Scratch (device globals; no allocation allowed)
__device__ float g_A[NROWS * HH];     // vecs @ W1[0:768]
__device__ float g_C[NROWS * HH];     // vecs @ W1[768:1536] + b1
__device__ float g_M[BB * NSPLIT * LL];
__device__ float g_S[BB * NSPLIT * LL];
__device__ float g_LSE[BB * LL];

// ---------------------------------------------------------------------------
// Kernel 1: pre-GEMM.  out[r][h] = sum_d vecs[r][d] * W1p[d][h]  (+ b1 for C)
// grid (13, 8, 2), block 256.  z=0 -> A part, z=1 -> C part.
// ---------------------------------------------------------------------------
__global__ void gemm_w1_kernel(const float* __restrict__ hidden,
                               const float* __restrict__ W1,
                               const float* __restrict__ b1)
{
    const int bn = blockIdx.x * 64;
    const int bm = blockIdx.y * 64;
    const bool isC = (blockIdx.z == 1);
    const float* Wp = W1 + (isC ? (size_t)DD * HH : 0);
    float* outp = isC ? g_C : g_A;

    __shared__ float sX[64][17];   // [m][k], padded
    __shared__ float sW[16][64];   // [k][n]

    const int tid = threadIdx.x;
    const int tx = tid & 15;       // n-dir
    const int ty = tid >> 4;       // m-dir

    float acc[4][4] = {};

    for (int kk = 0; kk < DD; kk += 16) {
        // load X chunk: 64 rows x 16 cols
        {
            int c = tid & 15;
            int m0 = tid >> 4;
            #pragma unroll
            for (int q = 0; q < 4; q++) {
                int m = m0 + q * 16;
                int r = bm + m;
                int b = r >> 7, t = r & 127;
                sX[m][c] = hidden[((size_t)(b * (TT + 1) + t + 1)) * DD + kk + c];
            }
        }
        // load W chunk: 16 rows x 64 cols
        {
            int n  = tid & 63;
            int k0 = (tid >> 6) * 4;
            int h  = bn + n;
            #pragma unroll
            for (int q = 0; q < 4; q++) {
                int k = k0 + q;
                sW[k][n] = (h < HH) ? Wp[(size_t)(kk + k) * HH + h] : 0.f;
            }
        }
        __syncthreads();
        #pragma unroll
        for (int k = 0; k < 16; k++) {
            float xr[4];
            #pragma unroll
            for (int i = 0; i < 4; i++) xr[i] = sX[ty * 4 + i][k];
            float4 wv = *reinterpret_cast<const float4*>(&sW[k][tx * 4]);
            float wr[4] = {wv.x, wv.y, wv.z, wv.w};
            #pragma unroll
            for (int i = 0; i < 4; i++)
                #pragma unroll
                for (int j = 0; j < 4; j++)
                    acc[i][j] = fmaf(xr[i], wr[j], acc[i][j]);
        }
        __syncthreads();
    }

    #pragma unroll
    for (int i = 0; i < 4; i++) {
        int r = bm + ty * 4 + i;
        #pragma unroll
        for (int j = 0; j < 4; j++) {
            int h = bn + tx * 4 + j;
            if (h < HH) {
                float v = acc[i][j];
                if (isC) v += b1[h];
                outp[(size_t)r * HH + h] = v;
            }
        }
    }
}

// ---------------------------------------------------------------------------
// Kernel 2: fused pair kernel.
// For block (b,i): out[b, i*T+j, l] = masked( relu(A_i + C_j + ind*w1last) @ W2 + b2 )
// grid 512, block 256 (tx 0..31 -> 4 strided j each; ty 0..7 -> 5 l each)
// ---------------------------------------------------------------------------
__global__ void pair_kernel(const float* __restrict__ W1,
                            const float* __restrict__ W2,
                            const float* __restrict__ b2,
                            const int*   __restrict__ pred_spans,
                            const int*   __restrict__ span_avail,
                            float* __restrict__ out)
{
    const int bi = blockIdx.x;
    const int b = bi >> 7;
    const int i = bi & 127;

    __shared__ float sC[128 * 33];
    __shared__ float sW2[32 * 41];
    __shared__ float sAi[32];
    __shared__ float sWl[32];      // W1 last row chunk (ind weights)
    __shared__ float sInd[128];

    const int tid = threadIdx.x;
    const int tx = tid & 31;
    const int ty = tid >> 5;
    const int l0 = ty * 5;

    if (tid < 128) {
        int s = pred_spans[b * 2 + 0];
        int e = pred_spans[b * 2 + 1];
        int j = tid;
        bool isfull = (i == s) && (j == e);
        bool inside = (s <= i) && (i <= j) && (j <= e) && !isfull;
        sInd[j] = isfull ? 2.f : (inside ? 1.f : 0.f);
    }
    __syncthreads();

    float indr[4];
    #pragma unroll
    for (int r = 0; r < 4; r++) indr[r] = sInd[tx + 32 * r];
    float b2r[5];
    #pragma unroll
    for (int q = 0; q < 5; q++) b2r[q] = b2[l0 + q];

    float acc[4][5] = {};

    const float* Arow  = g_A + (size_t)bi * HH;
    const float* Crow0 = g_C + (size_t)(b * TT) * HH;
    const float* w1last = W1 + (size_t)(2 * DD) * HH;   // row 1536 of W1

    for (int hc = 0; hc < HH; hc += 32) {
        if (tid < 32) {
            int h = hc + tid;
            sAi[tid] = (h < HH) ? Arow[h] : 0.f;
            sWl[tid] = (h < HH) ? w1last[h] : 0.f;
        }
        #pragma unroll
        for (int k = 0; k < 16; k++) {
            int lin = tid + 256 * k;            // 0..4095
            int j = lin >> 5, hk = lin & 31;
            int h = hc + hk;
            sC[j * 33 + hk] = (h < HH) ? Crow0[(size_t)j * HH + h] : 0.f;
        }
        for (int idx = tid; idx < 1280; idx += 256) {
            int h = hc + idx / 40;
            sW2[(idx / 40) * 41 + (idx % 40)] = (h < HH) ? W2[(size_t)hc * LL + idx] : 0.f;
        }
        __syncthreads();

        #pragma unroll
        for (int hk = 0; hk < 32; hk++) {
            float a  = sAi[hk];
            float wl = sWl[hk];
            float hv[4];
            #pragma unroll
            for (int r = 0; r < 4; r++) {
                float c = sC[(tx + 32 * r) * 33 + hk];
                hv[r] = fmaxf(fmaf(indr[r], wl, a + c), 0.f);
            }
            #pragma unroll
            for (int q = 0; q < 5; q++) {
                float w = sW2[hk * 41 + l0 + q];
                #pragma unroll
                for (int r = 0; r < 4; r++)
                    acc[r][q] = fmaf(hv[r], w, acc[r][q]);
            }
        }
        __syncthreads();
    }

    #pragma unroll
    for (int r = 0; r < 4; r++) {
        int j = tx + 32 * r;
        int msk = span_avail[i * TT + j];
        size_t base = ((size_t)(b * PP + i * TT + j)) * LL;
        #pragma unroll
        for (int q = 0; q < 5; q++) {
            float v = (msk >= 1) ? (acc[r][q] + b2r[q]) : 0.f;
            out[base + l0 + q] = v;
        }
    }
}

// ---------------------------------------------------------------------------
// Kernel 3a: partial log-sum-exp over pair axis (streaming max/sum).
// grid (NSPLIT, B), block 320 = 40 l x 8 q
// ---------------------------------------------------------------------------
__global__ void lse_partial_kernel(const float* __restrict__ out)
{
    const int b = blockIdx.y, split = blockIdx.x;
    const int t = threadIdx.x;
    const int l = t % 40, q = t / 40;
    const int p0 = split * PCHUNK;

    float m = -INFINITY, s = 0.f;
    for (int k = q; k < PCHUNK; k += 8) {
        float x = out[((size_t)b * PP + p0 + k) * LL + l];
        float mn = fmaxf(m, x);
        s = s * expf(m - mn) + expf(x - mn);
        m = mn;
    }
    __shared__ float sm[8][40], ss[8][40];
    sm[q][l] = m; ss[q][l] = s;
    __syncthreads();
    if (q == 0) {
        #pragma unroll
        for (int k = 1; k < 8; k++) {
            float m2 = sm[k][l], s2 = ss[k][l];
            float mn = fmaxf(m, m2);
            s = s * expf(m - mn) + s2 * expf(m2 - mn);
            m = mn;
        }
        g_M[(b * NSPLIT + split) * LL + l] = m;
        g_S[(b * NSPLIT + split) * LL + l] = s;
    }
}

// Kernel 3b: combine partials -> g_LSE.  1 block, 256 threads (160 active)
__global__ void lse_combine_kernel()
{
    int t = threadIdx.x;
    if (t < BB * LL) {
        int b = t / LL, l = t % LL;
        float m = -INFINITY, s = 0.f;
        for (int k = 0; k < NSPLIT; k++) {
            float m2 = g_M[(b * NSPLIT + k) * LL + l];
            float s2 = g_S[(b * NSPLIT + k) * LL + l];
            float mn = fmaxf(m, m2);
            s = s * expf(m - mn) + s2 * expf(m2 - mn);
            m = mn;
        }
        g_LSE[t] = m + logf(s);
    }
}

// Kernel 4: out -= lse.  grid (2560, B), block 256
__global__ void sub_lse_kernel(float* __restrict__ out)
{
    int b = blockIdx.y;
    int idx = blockIdx.x * 256 + threadIdx.x;
    if (idx < PP * LL) {
        int l = idx % LL;
        size_t g = (size_t)b * PP * LL + idx;
        out[g] -= g_LSE[b * LL + l];
    }
}

// ---------------------------------------------------------------------------
extern "C" void kernel_launch(void* const* d_in, const int* in_sizes, int n_in,
                              void* d_out, int out_size)
{
    const float* hidden     = (const float*)d_in[0];
    const float* W1         = (const float*)d_in[1];
    const float* b1         = (const float*)d_in[2];
    const float* W2         = (const float*)d_in[3];
    const float* b2         = (const float*)d_in[4];
    const int*   pred_spans = (const int*)d_in[5];
    const int*   span_avail = (const int*)d_in[6];
    float* out = (float*)d_out;

    gemm_w1_kernel<<<dim3(13, 8, 2), 256>>>(hidden, W1, b1);
    pair_kernel<<<NROWS, 256>>>(W1, W2, b2, pred_spans, span_avail, out);
    lse_partial_kernel<<<dim3(NSPLIT, BB), 320>>>(out);
    lse_combine_kernel<<<1, 256>>>();
    sub_lse_kernel<<<dim3((PP * LL + 255) / 256, BB), 256>>>(out);
}

// round 3
// speedup vs baseline: 2.3477x; 2.3477x over previous
#include <cuda_runtime.h>
#include <cuda_bf16.h>
#include <math.h>
#include <stdint.h>

// Problem constants (fixed shapes)
#define BB 4
#define TT 128
#define DD 768
#define HH 770
#define LL 40
#define PP (TT*TT)          // 16384 pairs per batch
#define NROWS (BB*TT)       // 512
#define RS 784              // padded row stride for g_A/g_C
#define NSPLIT 16
#define PCHUNK (PP/NSPLIT)  // 1024

#define KC 128              // K chunk for MMA
#define NCH 6               // 6*128 = 768 via MMA; hidden units 768,769 in epilogue
#define HSTRIDE 272         // bytes per H-tile row (128 bf16 + 8 pad), multiple of 16
#define B_CHUNK_BYTES 10240 // 80 packed 8x8 bf16 matrices * 128B

// Scratch (device globals; no allocation allowed)
__device__ float g_A[NROWS * RS];                 // vecs @ W1[0:768]
__device__ float g_C[NROWS * RS];                 // vecs @ W1[768:1536] + b1
__device__ __nv_bfloat16 g_W2b[DD * LL];          // bf16 W2 rows 0..767
__device__ float g_M[BB * NSPLIT * LL];
__device__ float g_S[BB * NSPLIT * LL];
__device__ float g_LSE[BB * LL];

__device__ __forceinline__ uint32_t smem_u32(const void* p) {
    uint32_t a;
    asm("{ .reg .u64 t; cvta.to.shared.u64 t, %1; cvt.u32.u64 %0, t; }" : "=r"(a) : "l"(p));
    return a;
}

// ---------------------------------------------------------------------------
// Kernel 0: convert W2[0:768] to bf16
// ---------------------------------------------------------------------------
__global__ void w2b_prep_kernel(const float* __restrict__ W2)
{
    int e = blockIdx.x * 256 + threadIdx.x;
    if (e < DD * LL) g_W2b[e] = __float2bfloat16(W2[e]);
}

// ---------------------------------------------------------------------------
// Kernel 1: pre-GEMM.  out[r][h] = sum_d vecs[r][d] * W1p[d][h]  (+ b1 for C)
// ---------------------------------------------------------------------------
__global__ void gemm_w1_kernel(const float* __restrict__ hidden,
                               const float* __restrict__ W1,
                               const float* __restrict__ b1)
{
    const int bn = blockIdx.x * 64;
    const int bm = blockIdx.y * 64;
    const bool isC = (blockIdx.z == 1);
    const float* Wp = W1 + (isC ? (size_t)DD * HH : 0);
    float* outp = isC ? g_C : g_A;

    __shared__ float sX[64][17];
    __shared__ float sW[16][64];

    const int tid = threadIdx.x;
    const int tx = tid & 15;
    const int ty = tid >> 4;

    float acc[4][4] = {};

    for (int kk = 0; kk < DD; kk += 16) {
        {
            int c = tid & 15;
            int m0 = tid >> 4;
            #pragma unroll
            for (int q = 0; q < 4; q++) {
                int m = m0 + q * 16;
                int r = bm + m;
                int b = r >> 7, t = r & 127;
                sX[m][c] = hidden[((size_t)(b * (TT + 1) + t + 1)) * DD + kk + c];
            }
        }
        {
            int n  = tid & 63;
            int k0 = (tid >> 6) * 4;
            int h  = bn + n;
            #pragma unroll
            for (int q = 0; q < 4; q++) {
                int k = k0 + q;
                sW[k][n] = (h < HH) ? Wp[(size_t)(kk + k) * HH + h] : 0.f;
            }
        }
        __syncthreads();
        #pragma unroll
        for (int k = 0; k < 16; k++) {
            float xr[4];
            #pragma unroll
            for (int i = 0; i < 4; i++) xr[i] = sX[ty * 4 + i][k];
            float4 wv = *reinterpret_cast<const float4*>(&sW[k][tx * 4]);
            float wr[4] = {wv.x, wv.y, wv.z, wv.w};
            #pragma unroll
            for (int i = 0; i < 4; i++)
                #pragma unroll
                for (int j = 0; j < 4; j++)
                    acc[i][j] = fmaf(xr[i], wr[j], acc[i][j]);
        }
        __syncthreads();
    }

    #pragma unroll
    for (int i = 0; i < 4; i++) {
        int r = bm + ty * 4 + i;
        #pragma unroll
        for (int j = 0; j < 4; j++) {
            int h = bn + tx * 4 + j;
            if (h < HH) {
                float v = acc[i][j];
                if (isC) v += b1[h];
                outp[(size_t)r * RS + h] = v;
            }
        }
    }
}

// ---------------------------------------------------------------------------
// Kernel 2: fused pair kernel with mma.sync (bf16 HMMA).
// Block (b,i): D[j,l] = relu(A_i + C_j + ind*wl)[0:768] @ W2[0:768]
// plus epilogue terms for hidden units 768,769; + b2; mask; store.
// Warp w owns j-rows w*16..w*16+15; accumulators in registers.
// ---------------------------------------------------------------------------
__global__ void __launch_bounds__(256) pair_mma_kernel(
        const float* __restrict__ W1,
        const float* __restrict__ W2,
        const float* __restrict__ b2,
        const int*   __restrict__ pred_spans,
        const int*   __restrict__ span_avail,
        float* __restrict__ out)
{
    __shared__ __align__(16) unsigned char sH[TT * HSTRIDE];      // 34816 B
    __shared__ __align__(16) unsigned char sB[B_CHUNK_BYTES];     // 10240 B
    __shared__ float sInd[TT];
    __shared__ float sW2a[LL], sW2b[LL], sB2[LL];

    const int tid = threadIdx.x;
    const int wid = tid >> 5;
    const int lid = tid & 31;
    const int bi = blockIdx.x;
    const int b = bi >> 7;
    const int i = bi & 127;

    // Span indicator per j + epilogue constants
    if (tid < TT) {
        int s = pred_spans[b * 2 + 0];
        int e = pred_spans[b * 2 + 1];
        int j = tid;
        bool isfull = (i == s) && (j == e);
        bool inside = (s <= i) && (i <= j) && (j <= e) && !isfull;
        sInd[j] = isfull ? 2.f : (inside ? 1.f : 0.f);
    }
    if (tid < LL) {
        sW2a[tid] = W2[(size_t)768 * LL + tid];
        sW2b[tid] = W2[(size_t)769 * LL + tid];
        sB2[tid]  = b2[tid];
    }
    __syncthreads();

    const float* Arow  = g_A + (size_t)bi * RS;
    const float* Cbase = g_C + (size_t)(b * TT) * RS;
    const float* wlrow = W1 + (size_t)(2 * DD) * HH;   // W1 row 1536

    float acc[5][4] = {};   // 5 n-tiles x 4 f32 per m16n8 C fragment

    const uint32_t sH_base = smem_u32(sH);
    const uint32_t sB_base = smem_u32(sB);

    // ldmatrix source addresses (fixed per thread, advance by chunk内 offsets)
    // A: rows j0 + (lane&15), col-quad (lane>>4)*16 bytes
    const uint32_t aAddrBase = sH_base + (uint32_t)((wid * 16 + (lid & 15)) * HSTRIDE + (lid >> 4) * 16);
    // B packed: block = ((ks*2 + half)*5 + nt), row (lane&7)*16
    const uint32_t bHalf = (lid >> 3) & 1;
    const uint32_t bRow  = (lid & 7) * 16;

    for (int cc = 0; cc < NCH; cc++) {
        // ---- stage B chunk (packed ldmatrix layout) ----
        {
            const uint32_t* src = (const uint32_t*)g_W2b + cc * KC * (LL / 2);
            #pragma unroll
            for (int q = 0; q < 10; q++) {
                int e = tid + q * 256;          // 0..2559
                int k = e / 20, np = e % 20;
                int n = np * 2;
                int blockb = ((k >> 4) * 2 + ((k >> 3) & 1)) * 5 + (n >> 3);
                int byte = blockb * 128 + (k & 7) * 16 + (n & 7) * 2;
                *(uint32_t*)(sB + byte) = src[k * 20 + np];
            }
        }
        __syncthreads();

        // ---- produce H chunk: warp wid covers j = wid*16..+15, lane covers 4 k ----
        {
            const int k4 = lid * 4;
            const float4 a4 = *(const float4*)(Arow + cc * KC + k4);
            const float4 w4 = *(const float4*)(wlrow + cc * KC + k4);
            #pragma unroll
            for (int r = 0; r < 16; r++) {
                const int j = wid * 16 + r;
                const float ind = sInd[j];
                const float4 c4 = *(const float4*)(Cbase + (size_t)j * RS + cc * KC + k4);
                float h0 = fmaxf(fmaf(ind, w4.x, a4.x + c4.x), 0.f);
                float h1 = fmaxf(fmaf(ind, w4.y, a4.y + c4.y), 0.f);
                float h2 = fmaxf(fmaf(ind, w4.z, a4.z + c4.z), 0.f);
                float h3 = fmaxf(fmaf(ind, w4.w, a4.w + c4.w), 0.f);
                uint32_t u0, u1;
                asm("cvt.rn.bf16x2.f32 %0, %1, %2;" : "=r"(u0) : "f"(h1), "f"(h0));
                asm("cvt.rn.bf16x2.f32 %0, %1, %2;" : "=r"(u1) : "f"(h3), "f"(h2));
                asm volatile("st.shared.v2.b32 [%0], {%1, %2};"
                             :: "r"(sH_base + (uint32_t)(j * HSTRIDE + k4 * 2)), "r"(u0), "r"(u1) : "memory");
            }
        }
        __syncthreads();

        // ---- MMA over this chunk: 8 k-steps x 5 n-tiles ----
        #pragma unroll
        for (int ks = 0; ks < 8; ks++) {
            uint32_t a0, a1, a2, a3;
            asm volatile("ldmatrix.sync.aligned.m8n8.x4.shared.b16 {%0,%1,%2,%3}, [%4];"
                : "=r"(a0), "=r"(a1), "=r"(a2), "=r"(a3)
                : "r"(aAddrBase + (uint32_t)(ks * 32)));
            #pragma unroll
            for (int nt = 0; nt < 5; nt++) {
                uint32_t b0, b1;
                uint32_t baddr = sB_base + (uint32_t)(((ks * 2 + bHalf) * 5 + nt) * 128) + bRow;
                asm volatile("ldmatrix.sync.aligned.m8n8.x2.trans.shared.b16 {%0,%1}, [%2];"
                    : "=r"(b0), "=r"(b1) : "r"(baddr));
                asm volatile("mma.sync.aligned.m16n8k16.row.col.f32.bf16.bf16.f32 "
                    "{%0,%1,%2,%3}, {%4,%5,%6,%7}, {%8,%9}, {%0,%1,%2,%3};"
                    : "+f"(acc[nt][0]), "+f"(acc[nt][1]), "+f"(acc[nt][2]), "+f"(acc[nt][3])
                    : "r"(a0), "r"(a1), "r"(a2), "r"(a3), "r"(b0), "r"(b1));
            }
        }
        __syncthreads();
    }

    // ---- epilogue ----
    // C frag mapping: c0/c1 -> row j0+(lane>>2), cols nt*8+(lane&3)*2 +{0,1}; c2/c3 -> row +8
    {
        const int lcol = (lid & 3) * 2;
        const float wl768 = wlrow[768], wl769 = wlrow[769];
        const float a768 = Arow[768], a769 = Arow[769];
        #pragma unroll
        for (int half = 0; half < 2; half++) {
            const int j = wid * 16 + (lid >> 2) + half * 8;
            const float ind = sInd[j];
            const float2 cx = *(const float2*)(Cbase + (size_t)j * RS + 768);
            const float h768 = fmaxf(fmaf(ind, wl768, a768 + cx.x), 0.f);
            const float h769 = fmaxf(fmaf(ind, wl769, a769 + cx.y), 0.f);
            const bool msk = span_avail[i * TT + j] >= 1;
            float* orow = out + ((size_t)(b * PP + i * TT + j)) * LL;
            #pragma unroll
            for (int nt = 0; nt < 5; nt++) {
                const int col = nt * 8 + lcol;
                float2 v;
                float r0 = acc[nt][half * 2 + 0];
                float r1 = acc[nt][half * 2 + 1];
                v.x = msk ? (r0 + sB2[col]     + h768 * sW2a[col]     + h769 * sW2b[col])     : 0.f;
                v.y = msk ? (r1 + sB2[col + 1] + h768 * sW2a[col + 1] + h769 * sW2b[col + 1]) : 0.f;
                *(float2*)(orow + col) = v;
            }
        }
    }
}

// ---------------------------------------------------------------------------
// Kernel 3a: partial log-sum-exp over pair axis (streaming max/sum).
// ---------------------------------------------------------------------------
__global__ void lse_partial_kernel(const float* __restrict__ out)
{
    const int b = blockIdx.y, split = blockIdx.x;
    const int t = threadIdx.x;
    const int l = t % 40, q = t / 40;
    const int p0 = split * PCHUNK;

    float m = -INFINITY, s = 0.f;
    for (int k = q; k < PCHUNK; k += 8) {
        float x = out[((size_t)b * PP + p0 + k) * LL + l];
        float mn = fmaxf(m, x);
        s = s * expf(m - mn) + expf(x - mn);
        m = mn;
    }
    __shared__ float sm[8][40], ss[8][40];
    sm[q][l] = m; ss[q][l] = s;
    __syncthreads();
    if (q == 0) {
        #pragma unroll
        for (int k = 1; k < 8; k++) {
            float m2 = sm[k][l], s2 = ss[k][l];
            float mn = fmaxf(m, m2);
            s = s * expf(m - mn) + s2 * expf(m2 - mn);
            m = mn;
        }
        g_M[(b * NSPLIT + split) * LL + l] = m;
        g_S[(b * NSPLIT + split) * LL + l] = s;
    }
}

// Kernel 3b: combine partials -> g_LSE
__global__ void lse_combine_kernel()
{
    int t = threadIdx.x;
    if (t < BB * LL) {
        int b = t / LL, l = t % LL;
        float m = -INFINITY, s = 0.f;
        #pragma unroll
        for (int k = 0; k < NSPLIT; k++) {
            float m2 = g_M[(b * NSPLIT + k) * LL + l];
            float s2 = g_S[(b * NSPLIT + k) * LL + l];
            float mn = fmaxf(m, m2);
            s = s * expf(m - mn) + s2 * expf(m2 - mn);
            m = mn;
        }
        g_LSE[t] = m + logf(s);
    }
}

// Kernel 4: out -= lse
__global__ void sub_lse_kernel(float* __restrict__ out)
{
    int b = blockIdx.y;
    int idx = blockIdx.x * 256 + threadIdx.x;
    if (idx < PP * LL) {
        int l = idx % LL;
        size_t g = (size_t)b * PP * LL + idx;
        out[g] -= g_LSE[b * LL + l];
    }
}

// ---------------------------------------------------------------------------
extern "C" void kernel_launch(void* const* d_in, const int* in_sizes, int n_in,
                              void* d_out, int out_size)
{
    const float* hidden     = (const float*)d_in[0];
    const float* W1         = (const float*)d_in[1];
    const float* b1         = (const float*)d_in[2];
    const float* W2         = (const float*)d_in[3];
    const float* b2         = (const float*)d_in[4];
    const int*   pred_spans = (const int*)d_in[5];
    const int*   span_avail = (const int*)d_in[6];
    float* out = (float*)d_out;

    w2b_prep_kernel<<<(DD * LL + 255) / 256, 256>>>(W2);
    gemm_w1_kernel<<<dim3(13, 8, 2), 256>>>(hidden, W1, b1);
    pair_mma_kernel<<<NROWS, 256>>>(W1, W2, b2, pred_spans, span_avail, out);
    lse_partial_kernel<<<dim3(NSPLIT, BB), 320>>>(out);
    lse_combine_kernel<<<1, 256>>>();
    sub_lse_kernel<<<dim3((PP * LL + 255) / 256, BB), 256>>>(out);
}

// round 4
// speedup vs baseline: 3.4951x; 1.4887x over previous
#include <cuda_runtime.h>
#include <cuda_bf16.h>
#include <math.h>
#include <stdint.h>

// Problem constants (fixed shapes)
#define BB 4
#define TT 128
#define DD 768
#define HH 770
#define LL 40
#define PP (TT*TT)          // 16384 pairs per batch
#define NROWS (BB*TT)       // 512
#define RS 784              // padded row stride for g_A/g_C

#define KC 128              // K chunk for pair MMA
#define NCH 6               // 6*128 = 768 via MMA; hidden units 768,769 in epilogue
#define HSTRIDE 272         // bytes per H-tile row (128 bf16 + 8 pad)
#define B_CHUNK_BYTES 10240 // 80 packed 8x8 bf16 matrices * 128B

// Scratch (device globals; no allocation allowed)
__device__ float g_A[NROWS * RS];                 // vecs @ W1[0:768]
__device__ float g_C[NROWS * RS];                 // vecs @ W1[768:1536] + b1
__device__ __nv_bfloat16 g_W2b[DD * LL];          // bf16 W2 rows 0..767
__device__ float g_M[NROWS * LL];                 // per-(b,i) partial max
__device__ float g_S[NROWS * LL];                 // per-(b,i) partial sumexp
__device__ __align__(16) float g_LSE[BB * LL];

__device__ __forceinline__ uint32_t smem_u32(const void* p) {
    uint32_t a;
    asm("{ .reg .u64 t; cvta.to.shared.u64 t, %1; cvt.u32.u64 %0, t; }" : "=r"(a) : "l"(p));
    return a;
}
__device__ __forceinline__ float to_tf32(float x) {
    uint32_t u;
    asm("cvt.rna.tf32.f32 %0, %1;" : "=r"(u) : "f"(x));
    return __uint_as_float(u);
}

// ---------------------------------------------------------------------------
// Kernel 0: convert W2[0:768] to bf16
// ---------------------------------------------------------------------------
__global__ void w2b_prep_kernel(const float* __restrict__ W2)
{
    int e = blockIdx.x * 256 + threadIdx.x;
    if (e < DD * LL) g_W2b[e] = __float2bfloat16(W2[e]);
}

// ---------------------------------------------------------------------------
// Kernel 1: pre-GEMM via tf32 mma.sync.
// X[512x768] @ W1part[768x770] -> g_A / g_C (+b1).  Block tile 128m x 64n.
// grid (13, 4, 2), block 256 (8 warps, each warp: m16 x n64)
// ---------------------------------------------------------------------------
#define GXS 36   // sX row stride (floats)
#define GWS 72   // sW row stride (floats)
__global__ void __launch_bounds__(256) gemm_w1_tf32_kernel(
        const float* __restrict__ hidden,
        const float* __restrict__ W1,
        const float* __restrict__ b1)
{
    const int bn = blockIdx.x * 64;
    const int bm = blockIdx.y * 128;
    const bool isC = (blockIdx.z == 1);
    const float* Wp = W1 + (isC ? (size_t)DD * HH : 0);
    float* outp = isC ? g_C : g_A;

    __shared__ __align__(16) float sX[128 * GXS];   // 18432 B
    __shared__ __align__(16) float sW[32 * GWS];    // 9216 B

    const int tid = threadIdx.x;
    const int wid = tid >> 5;
    const int lid = tid & 31;
    const int m0 = wid * 16;
    const int gq = lid >> 2;      // groupID
    const int tg = lid & 3;       // thread-in-group

    float acc[8][4] = {};

    for (int kk = 0; kk < DD; kk += 32) {
        // stage X: 128 rows x 32 cols (tf32-rounded)
        #pragma unroll
        for (int q = 0; q < 4; q++) {
            int idx = tid + q * 256;          // 0..1023
            int row = idx >> 3, c4 = (idx & 7) * 4;
            int gm = bm + row;
            int b = gm >> 7, t = gm & 127;
            float4 v = *(const float4*)(hidden + ((size_t)(b * (TT + 1) + t + 1)) * DD + kk + c4);
            v.x = to_tf32(v.x); v.y = to_tf32(v.y); v.z = to_tf32(v.z); v.w = to_tf32(v.w);
            *(float4*)(sX + row * GXS + c4) = v;
        }
        // stage W: 32 k-rows x 64 n-cols (guarded, tf32-rounded)
        #pragma unroll
        for (int q = 0; q < 2; q++) {
            int idx = tid + q * 256;          // 0..511
            int k = idx >> 4, c4 = (idx & 15) * 4;
            const float* wrow = Wp + (size_t)(kk + k) * HH;
            float4 v;
            int n0 = bn + c4;
            v.x = (n0 + 0 < HH) ? to_tf32(wrow[n0 + 0]) : 0.f;
            v.y = (n0 + 1 < HH) ? to_tf32(wrow[n0 + 1]) : 0.f;
            v.z = (n0 + 2 < HH) ? to_tf32(wrow[n0 + 2]) : 0.f;
            v.w = (n0 + 3 < HH) ? to_tf32(wrow[n0 + 3]) : 0.f;
            *(float4*)(sW + k * GWS + c4) = v;
        }
        __syncthreads();

        #pragma unroll
        for (int ks = 0; ks < 4; ks++) {
            const int kb = ks * 8;
            uint32_t a0 = __float_as_uint(sX[(m0 + gq) * GXS + kb + tg]);
            uint32_t a1 = __float_as_uint(sX[(m0 + gq + 8) * GXS + kb + tg]);
            uint32_t a2 = __float_as_uint(sX[(m0 + gq) * GXS + kb + tg + 4]);
            uint32_t a3 = __float_as_uint(sX[(m0 + gq + 8) * GXS + kb + tg + 4]);
            #pragma unroll
            for (int nt = 0; nt < 8; nt++) {
                uint32_t b0 = __float_as_uint(sW[(kb + tg) * GWS + nt * 8 + gq]);
                uint32_t b1 = __float_as_uint(sW[(kb + tg + 4) * GWS + nt * 8 + gq]);
                asm volatile("mma.sync.aligned.m16n8k8.row.col.f32.tf32.tf32.f32 "
                    "{%0,%1,%2,%3}, {%4,%5,%6,%7}, {%8,%9}, {%0,%1,%2,%3};"
                    : "+f"(acc[nt][0]), "+f"(acc[nt][1]), "+f"(acc[nt][2]), "+f"(acc[nt][3])
                    : "r"(a0), "r"(a1), "r"(a2), "r"(a3), "r"(b0), "r"(b1));
            }
        }
        __syncthreads();
    }

    // epilogue
    #pragma unroll
    for (int half = 0; half < 2; half++) {
        int gm = bm + m0 + gq + half * 8;
        #pragma unroll
        for (int nt = 0; nt < 8; nt++) {
            int gn = bn + nt * 8 + tg * 2;
            float v0 = acc[nt][half * 2 + 0];
            float v1 = acc[nt][half * 2 + 1];
            if (gn < HH)     outp[(size_t)gm * RS + gn]     = v0 + (isC ? b1[gn]     : 0.f);
            if (gn + 1 < HH) outp[(size_t)gm * RS + gn + 1] = v1 + (isC ? b1[gn + 1] : 0.f);
        }
    }
}

// ---------------------------------------------------------------------------
// Kernel 2: fused pair kernel (bf16 HMMA) + per-block LSE partial reduction.
// ---------------------------------------------------------------------------
__global__ void __launch_bounds__(256) pair_mma_kernel(
        const float* __restrict__ W1,
        const float* __restrict__ W2,
        const float* __restrict__ b2,
        const int*   __restrict__ pred_spans,
        const int*   __restrict__ span_avail,
        float* __restrict__ out)
{
    __shared__ __align__(16) unsigned char sH[TT * HSTRIDE];      // 34816 B
    __shared__ __align__(16) unsigned char sB[B_CHUNK_BYTES];     // 10240 B (reused for LSE merge)
    __shared__ float sInd[TT];
    __shared__ float sW2a[LL], sW2b[LL], sB2[LL];

    const int tid = threadIdx.x;
    const int wid = tid >> 5;
    const int lid = tid & 31;
    const int bi = blockIdx.x;
    const int b = bi >> 7;
    const int i = bi & 127;

    if (tid < TT) {
        int s = pred_spans[b * 2 + 0];
        int e = pred_spans[b * 2 + 1];
        int j = tid;
        bool isfull = (i == s) && (j == e);
        bool inside = (s <= i) && (i <= j) && (j <= e) && !isfull;
        sInd[j] = isfull ? 2.f : (inside ? 1.f : 0.f);
    }
    if (tid < LL) {
        sW2a[tid] = W2[(size_t)768 * LL + tid];
        sW2b[tid] = W2[(size_t)769 * LL + tid];
        sB2[tid]  = b2[tid];
    }
    __syncthreads();

    const float* Arow  = g_A + (size_t)bi * RS;
    const float* Cbase = g_C + (size_t)(b * TT) * RS;
    const float* wlrow = W1 + (size_t)(2 * DD) * HH;   // W1 row 1536

    float acc[5][4] = {};

    const uint32_t sH_base = smem_u32(sH);
    const uint32_t sB_base = smem_u32(sB);

    const uint32_t aAddrBase = sH_base + (uint32_t)((wid * 16 + (lid & 15)) * HSTRIDE + (lid >> 4) * 16);
    const uint32_t bHalf = (lid >> 3) & 1;
    const uint32_t bRow  = (lid & 7) * 16;

    for (int cc = 0; cc < NCH; cc++) {
        // stage B chunk (packed ldmatrix layout)
        {
            const uint32_t* src = (const uint32_t*)g_W2b + cc * KC * (LL / 2);
            #pragma unroll
            for (int q = 0; q < 10; q++) {
                int e = tid + q * 256;
                int k = e / 20, np = e % 20;
                int n = np * 2;
                int blockb = ((k >> 4) * 2 + ((k >> 3) & 1)) * 5 + (n >> 3);
                int byte = blockb * 128 + (k & 7) * 16 + (n & 7) * 2;
                *(uint32_t*)(sB + byte) = src[k * 20 + np];
            }
        }
        __syncthreads();

        // produce H chunk
        {
            const int k4 = lid * 4;
            const float4 a4 = *(const float4*)(Arow + cc * KC + k4);
            const float4 w4 = *(const float4*)(wlrow + cc * KC + k4);
            #pragma unroll
            for (int r = 0; r < 16; r++) {
                const int j = wid * 16 + r;
                const float ind = sInd[j];
                const float4 c4 = *(const float4*)(Cbase + (size_t)j * RS + cc * KC + k4);
                float h0 = fmaxf(fmaf(ind, w4.x, a4.x + c4.x), 0.f);
                float h1 = fmaxf(fmaf(ind, w4.y, a4.y + c4.y), 0.f);
                float h2 = fmaxf(fmaf(ind, w4.z, a4.z + c4.z), 0.f);
                float h3 = fmaxf(fmaf(ind, w4.w, a4.w + c4.w), 0.f);
                uint32_t u0, u1;
                asm("cvt.rn.bf16x2.f32 %0, %1, %2;" : "=r"(u0) : "f"(h1), "f"(h0));
                asm("cvt.rn.bf16x2.f32 %0, %1, %2;" : "=r"(u1) : "f"(h3), "f"(h2));
                asm volatile("st.shared.v2.b32 [%0], {%1, %2};"
                             :: "r"(sH_base + (uint32_t)(j * HSTRIDE + k4 * 2)), "r"(u0), "r"(u1) : "memory");
            }
        }
        __syncthreads();

        // MMA: 8 k-steps x 5 n-tiles
        #pragma unroll
        for (int ks = 0; ks < 8; ks++) {
            uint32_t a0, a1, a2, a3;
            asm volatile("ldmatrix.sync.aligned.m8n8.x4.shared.b16 {%0,%1,%2,%3}, [%4];"
                : "=r"(a0), "=r"(a1), "=r"(a2), "=r"(a3)
                : "r"(aAddrBase + (uint32_t)(ks * 32)));
            #pragma unroll
            for (int nt = 0; nt < 5; nt++) {
                uint32_t b0, b1;
                uint32_t baddr = sB_base + (uint32_t)(((ks * 2 + bHalf) * 5 + nt) * 128) + bRow;
                asm volatile("ldmatrix.sync.aligned.m8n8.x2.trans.shared.b16 {%0,%1}, [%2];"
                    : "=r"(b0), "=r"(b1) : "r"(baddr));
                asm volatile("mma.sync.aligned.m16n8k16.row.col.f32.bf16.bf16.f32 "
                    "{%0,%1,%2,%3}, {%4,%5,%6,%7}, {%8,%9}, {%0,%1,%2,%3};"
                    : "+f"(acc[nt][0]), "+f"(acc[nt][1]), "+f"(acc[nt][2]), "+f"(acc[nt][3])
                    : "r"(a0), "r"(a1), "r"(a2), "r"(a3), "r"(b0), "r"(b1));
            }
        }
        __syncthreads();
    }

    // ---- epilogue: finalize logits, store, and reduce LSE partials ----
    float vv[2][10];   // [half][nt*2 + {0,1}]
    {
        const int lcol = (lid & 3) * 2;
        const float wl768 = wlrow[768], wl769 = wlrow[769];
        const float a768 = Arow[768], a769 = Arow[769];
        #pragma unroll
        for (int half = 0; half < 2; half++) {
            const int j = wid * 16 + (lid >> 2) + half * 8;
            const float ind = sInd[j];
            const float2 cx = *(const float2*)(Cbase + (size_t)j * RS + 768);
            const float h768 = fmaxf(fmaf(ind, wl768, a768 + cx.x), 0.f);
            const float h769 = fmaxf(fmaf(ind, wl769, a769 + cx.y), 0.f);
            const bool msk = span_avail[i * TT + j] >= 1;
            float* orow = out + ((size_t)(b * PP + i * TT + j)) * LL;
            #pragma unroll
            for (int nt = 0; nt < 5; nt++) {
                const int col = nt * 8 + lcol;
                float r0 = acc[nt][half * 2 + 0];
                float r1 = acc[nt][half * 2 + 1];
                float2 v;
                v.x = msk ? (r0 + sB2[col]     + h768 * sW2a[col]     + h769 * sW2b[col])     : 0.f;
                v.y = msk ? (r1 + sB2[col + 1] + h768 * sW2a[col + 1] + h769 * sW2b[col + 1]) : 0.f;
                *(float2*)(orow + col) = v;
                vv[half][nt * 2 + 0] = v.x;
                vv[half][nt * 2 + 1] = v.y;
            }
        }
    }
    // per-warp reduction over the 16 j-rows (lane bits 2..4) for each of 10 cols
    float pm[10], ps[10];
    #pragma unroll
    for (int c = 0; c < 10; c++) {
        float m = fmaxf(vv[0][c], vv[1][c]);
        m = fmaxf(m, __shfl_xor_sync(0xffffffffu, m, 4));
        m = fmaxf(m, __shfl_xor_sync(0xffffffffu, m, 8));
        m = fmaxf(m, __shfl_xor_sync(0xffffffffu, m, 16));
        float s = __expf(vv[0][c] - m) + __expf(vv[1][c] - m);
        s += __shfl_xor_sync(0xffffffffu, s, 4);
        s += __shfl_xor_sync(0xffffffffu, s, 8);
        s += __shfl_xor_sync(0xffffffffu, s, 16);
        pm[c] = m; ps[c] = s;
    }
    // cross-warp merge via smem (reuse sB region; safe after last __syncthreads)
    float* sRm = (float*)sB;            // [8][40]
    float* sRs = sRm + 8 * LL;          // [8][40]
    if (lid < 4) {
        const int lcol = lid * 2;
        #pragma unroll
        for (int nt = 0; nt < 5; nt++) {
            sRm[wid * LL + nt * 8 + lcol]     = pm[nt * 2 + 0];
            sRm[wid * LL + nt * 8 + lcol + 1] = pm[nt * 2 + 1];
            sRs[wid * LL + nt * 8 + lcol]     = ps[nt * 2 + 0];
            sRs[wid * LL + nt * 8 + lcol + 1] = ps[nt * 2 + 1];
        }
    }
    __syncthreads();
    if (tid < LL) {
        float m = sRm[tid];
        #pragma unroll
        for (int w = 1; w < 8; w++) m = fmaxf(m, sRm[w * LL + tid]);
        float s = 0.f;
        #pragma unroll
        for (int w = 0; w < 8; w++) s += sRs[w * LL + tid] * __expf(sRm[w * LL + tid] - m);
        g_M[bi * LL + tid] = m;
        g_S[bi * LL + tid] = s;
    }
}

// ---------------------------------------------------------------------------
// Kernel 3: combine 128 partials per (b,l) -> g_LSE.  grid (40, 4), 128 thr
// ---------------------------------------------------------------------------
__global__ void lse_combine_kernel()
{
    const int l = blockIdx.x, b = blockIdx.y;
    const int t = threadIdx.x;
    __shared__ float sm[128], ss[128];
    sm[t] = g_M[(b * TT + t) * LL + l];
    ss[t] = g_S[(b * TT + t) * LL + l];
    __syncthreads();
    #pragma unroll
    for (int off = 64; off > 0; off >>= 1) {
        if (t < off) {
            float m1 = sm[t], m2 = sm[t + off];
            float mn = fmaxf(m1, m2);
            ss[t] = ss[t] * __expf(m1 - mn) + ss[t + off] * __expf(m2 - mn);
            sm[t] = mn;
        }
        __syncthreads();
    }
    if (t == 0) g_LSE[b * LL + l] = sm[0] + logf(ss[0]);
}

// ---------------------------------------------------------------------------
// Kernel 4: out -= lse (float4).  grid 2560, block 256
// ---------------------------------------------------------------------------
__global__ void sub_lse_kernel(float* __restrict__ out)
{
    int e = blockIdx.x * 256 + threadIdx.x;       // 0..655359 float4s
    int b = e / (PP * LL / 4);
    int r = e % (PP * LL / 4);
    int l0 = (r * 4) % LL;
    float4 lv = *(const float4*)(g_LSE + b * LL + l0);
    float4 v = ((const float4*)out)[e];
    v.x -= lv.x; v.y -= lv.y; v.z -= lv.z; v.w -= lv.w;
    ((float4*)out)[e] = v;
}

// ---------------------------------------------------------------------------
extern "C" void kernel_launch(void* const* d_in, const int* in_sizes, int n_in,
                              void* d_out, int out_size)
{
    const float* hidden     = (const float*)d_in[0];
    const float* W1         = (const float*)d_in[1];
    const float* b1         = (const float*)d_in[2];
    const float* W2         = (const float*)d_in[3];
    const float* b2         = (const float*)d_in[4];
    const int*   pred_spans = (const int*)d_in[5];
    const int*   span_avail = (const int*)d_in[6];
    float* out = (float*)d_out;

    w2b_prep_kernel<<<(DD * LL + 255) / 256, 256>>>(W2);
    gemm_w1_tf32_kernel<<<dim3(13, 4, 2), 256>>>(hidden, W1, b1);
    pair_mma_kernel<<<NROWS, 256>>>(W1, W2, b2, pred_spans, span_avail, out);
    lse_combine_kernel<<<dim3(LL, BB), 128>>>();
    sub_lse_kernel<<<(BB * PP * LL / 4) / 256, 256>>>(out);
}

// round 5
// speedup vs baseline: 4.2803x; 1.2247x over previous
#include <cuda_runtime.h>
#include <cuda_bf16.h>
#include <math.h>
#include <stdint.h>

// Problem constants (fixed shapes)
#define BB 4
#define TT 128
#define DD 768
#define HH 770
#define LL 40
#define PP (TT*TT)          // 16384 pairs per batch
#define NROWS (BB*TT)       // 512
#define RS 784              // padded row stride for g_A

#define KC 128              // K chunk for pair MMA
#define NCH 6               // 6*128 = 768 via MMA; hidden units 768,769 in epilogue
#define HSTRIDE 272         // bytes per H-tile row (128 bf16 + 8 pad)
#define B_CHUNK_BYTES 10240 // 80 packed 8x8 bf16 matrices * 128B
#define DYN_BYTES (2*TT*HSTRIDE + B_CHUNK_BYTES)   // 79872

// Scratch (device globals; no allocation allowed)
__device__ float g_A[NROWS * RS];                 // vecs @ W1[0:768] (fp32, cols 0..769)
__device__ __nv_bfloat16 g_Cb[NROWS * DD];        // vecs @ W1[768:1536] + b1, cols 0..767 (bf16)
__device__ float g_Ct[NROWS * 2];                 // C tail cols 768,769 (fp32)
__device__ __nv_bfloat16 g_W2b[DD * LL];          // bf16 W2 rows 0..767
__device__ float g_M[NROWS * LL];                 // per-(b,i) partial max
__device__ float g_S[NROWS * LL];                 // per-(b,i) partial sumexp
__device__ __align__(16) float g_LSE[BB * LL];

__device__ __forceinline__ uint32_t smem_u32(const void* p) {
    uint32_t a;
    asm("{ .reg .u64 t; cvta.to.shared.u64 t, %1; cvt.u32.u64 %0, t; }" : "=r"(a) : "l"(p));
    return a;
}
__device__ __forceinline__ float to_tf32(float x) {
    uint32_t u;
    asm("cvt.rna.tf32.f32 %0, %1;" : "=r"(u) : "f"(x));
    return __uint_as_float(u);
}

// ---------------------------------------------------------------------------
// Kernel 0: convert W2[0:768] to bf16
// ---------------------------------------------------------------------------
__global__ void w2b_prep_kernel(const float* __restrict__ W2)
{
    int e = blockIdx.x * 256 + threadIdx.x;
    if (e < DD * LL) g_W2b[e] = __float2bfloat16(W2[e]);
}

// ---------------------------------------------------------------------------
// Kernel 1: pre-GEMM via tf32 mma.sync.
// X[512x768] @ W1part[768x770] -> g_A (fp32) / g_Cb (bf16) + g_Ct.
// grid (13, 4, 2), block 256 (8 warps, each warp: m16 x n64)
// ---------------------------------------------------------------------------
#define GXS 36   // sX row stride (floats)
#define GWS 72   // sW row stride (floats)
__global__ void __launch_bounds__(256) gemm_w1_tf32_kernel(
        const float* __restrict__ hidden,
        const float* __restrict__ W1,
        const float* __restrict__ b1)
{
    const int bn = blockIdx.x * 64;
    const int bm = blockIdx.y * 128;
    const bool isC = (blockIdx.z == 1);
    const float* Wp = W1 + (isC ? (size_t)DD * HH : 0);

    __shared__ __align__(16) float sX[128 * GXS];   // 18432 B
    __shared__ __align__(16) float sW[32 * GWS];    // 9216 B

    const int tid = threadIdx.x;
    const int wid = tid >> 5;
    const int lid = tid & 31;
    const int m0 = wid * 16;
    const int gq = lid >> 2;      // groupID
    const int tg = lid & 3;       // thread-in-group

    float acc[8][4] = {};

    for (int kk = 0; kk < DD; kk += 32) {
        #pragma unroll
        for (int q = 0; q < 4; q++) {
            int idx = tid + q * 256;          // 0..1023
            int row = idx >> 3, c4 = (idx & 7) * 4;
            int gm = bm + row;
            int b = gm >> 7, t = gm & 127;
            float4 v = *(const float4*)(hidden + ((size_t)(b * (TT + 1) + t + 1)) * DD + kk + c4);
            v.x = to_tf32(v.x); v.y = to_tf32(v.y); v.z = to_tf32(v.z); v.w = to_tf32(v.w);
            *(float4*)(sX + row * GXS + c4) = v;
        }
        #pragma unroll
        for (int q = 0; q < 2; q++) {
            int idx = tid + q * 256;          // 0..511
            int k = idx >> 4, c4 = (idx & 15) * 4;
            const float* wrow = Wp + (size_t)(kk + k) * HH;
            float4 v;
            int n0 = bn + c4;
            v.x = (n0 + 0 < HH) ? to_tf32(wrow[n0 + 0]) : 0.f;
            v.y = (n0 + 1 < HH) ? to_tf32(wrow[n0 + 1]) : 0.f;
            v.z = (n0 + 2 < HH) ? to_tf32(wrow[n0 + 2]) : 0.f;
            v.w = (n0 + 3 < HH) ? to_tf32(wrow[n0 + 3]) : 0.f;
            *(float4*)(sW + k * GWS + c4) = v;
        }
        __syncthreads();

        #pragma unroll
        for (int ks = 0; ks < 4; ks++) {
            const int kb = ks * 8;
            uint32_t a0 = __float_as_uint(sX[(m0 + gq) * GXS + kb + tg]);
            uint32_t a1 = __float_as_uint(sX[(m0 + gq + 8) * GXS + kb + tg]);
            uint32_t a2 = __float_as_uint(sX[(m0 + gq) * GXS + kb + tg + 4]);
            uint32_t a3 = __float_as_uint(sX[(m0 + gq + 8) * GXS + kb + tg + 4]);
            #pragma unroll
            for (int nt = 0; nt < 8; nt++) {
                uint32_t b0 = __float_as_uint(sW[(kb + tg) * GWS + nt * 8 + gq]);
                uint32_t b1v = __float_as_uint(sW[(kb + tg + 4) * GWS + nt * 8 + gq]);
                asm volatile("mma.sync.aligned.m16n8k8.row.col.f32.tf32.tf32.f32 "
                    "{%0,%1,%2,%3}, {%4,%5,%6,%7}, {%8,%9}, {%0,%1,%2,%3};"
                    : "+f"(acc[nt][0]), "+f"(acc[nt][1]), "+f"(acc[nt][2]), "+f"(acc[nt][3])
                    : "r"(a0), "r"(a1), "r"(a2), "r"(a3), "r"(b0), "r"(b1v));
            }
        }
        __syncthreads();
    }

    // epilogue
    #pragma unroll
    for (int half = 0; half < 2; half++) {
        int gm = bm + m0 + gq + half * 8;
        #pragma unroll
        for (int nt = 0; nt < 8; nt++) {
            int gn = bn + nt * 8 + tg * 2;   // even
            float v0 = acc[nt][half * 2 + 0];
            float v1 = acc[nt][half * 2 + 1];
            if (!isC) {
                if (gn < HH)     g_A[(size_t)gm * RS + gn]     = v0;
                if (gn + 1 < HH) g_A[(size_t)gm * RS + gn + 1] = v1;
            } else {
                if (gn < DD) {
                    float w0 = v0 + b1[gn], w1 = v1 + b1[gn + 1];
                    uint32_t u;
                    asm("cvt.rn.bf16x2.f32 %0, %1, %2;" : "=r"(u) : "f"(w1), "f"(w0));
                    *(uint32_t*)(g_Cb + (size_t)gm * DD + gn) = u;
                } else if (gn < HH) {  // gn == 768
                    g_Ct[gm * 2 + 0] = v0 + b1[768];
                    g_Ct[gm * 2 + 1] = v1 + b1[769];
                }
            }
        }
    }
}

// ---------------------------------------------------------------------------
// Kernel 2: fused pair kernel (bf16 HMMA), 2 i-values per block + LSE partials.
// grid 256: block -> (b, i0=2*ip, i1=2*ip+1); warp w owns j-rows w*16..+15.
// ---------------------------------------------------------------------------
__global__ void __launch_bounds__(256) pair_mma_kernel(
        const float* __restrict__ W1,
        const float* __restrict__ W2,
        const float* __restrict__ b2,
        const int*   __restrict__ pred_spans,
        const int*   __restrict__ span_avail,
        float* __restrict__ out)
{
    extern __shared__ __align__(16) unsigned char dynsmem[];
    unsigned char* sH0 = dynsmem;                      // TT*HSTRIDE
    unsigned char* sH1 = dynsmem + TT * HSTRIDE;
    unsigned char* sB  = dynsmem + 2 * TT * HSTRIDE;   // B_CHUNK_BYTES (reused for LSE merge)

    __shared__ float sInd0[TT], sInd1[TT];
    __shared__ float sW2a[LL], sW2b[LL], sB2[LL];

    const int tid = threadIdx.x;
    const int wid = tid >> 5;
    const int lid = tid & 31;
    const int bi2 = blockIdx.x;
    const int b = bi2 >> 6;
    const int ip = bi2 & 63;
    const int i0 = ip * 2;
    const int i1 = ip * 2 + 1;
    const int bTT = b * TT;

    if (tid < TT) {
        int s = pred_spans[b * 2 + 0];
        int e = pred_spans[b * 2 + 1];
        int j = tid;
        bool f0 = (i0 == s) && (j == e);
        bool in0 = (s <= i0) && (i0 <= j) && (j <= e) && !f0;
        sInd0[j] = f0 ? 2.f : (in0 ? 1.f : 0.f);
        bool f1 = (i1 == s) && (j == e);
        bool in1 = (s <= i1) && (i1 <= j) && (j <= e) && !f1;
        sInd1[j] = f1 ? 2.f : (in1 ? 1.f : 0.f);
    }
    if (tid < LL) {
        sW2a[tid] = W2[(size_t)768 * LL + tid];
        sW2b[tid] = W2[(size_t)769 * LL + tid];
        sB2[tid]  = b2[tid];
    }
    __syncthreads();

    const float* Arow0 = g_A + (size_t)(bTT + i0) * RS;
    const float* Arow1 = g_A + (size_t)(bTT + i1) * RS;
    const float* wlrow = W1 + (size_t)(2 * DD) * HH;   // W1 row 1536

    float acc[2][5][4] = {};

    const uint32_t sH0_base = smem_u32(sH0);
    const uint32_t sB_base = smem_u32(sB);

    const uint32_t aAddr0 = sH0_base + (uint32_t)((wid * 16 + (lid & 15)) * HSTRIDE + (lid >> 4) * 16);
    const uint32_t aAddr1 = aAddr0 + (uint32_t)(TT * HSTRIDE);
    const uint32_t bHalf = (lid >> 3) & 1;
    const uint32_t bRow  = (lid & 7) * 16;

    for (int cc = 0; cc < NCH; cc++) {
        // stage B chunk (packed ldmatrix layout)
        {
            const uint32_t* src = (const uint32_t*)g_W2b + cc * KC * (LL / 2);
            #pragma unroll
            for (int q = 0; q < 10; q++) {
                int e = tid + q * 256;
                int k = e / 20, np = e % 20;
                int n = np * 2;
                int blockb = ((k >> 4) * 2 + ((k >> 3) & 1)) * 5 + (n >> 3);
                int byte = blockb * 128 + (k & 7) * 16 + (n & 7) * 2;
                *(uint32_t*)(sB + byte) = src[k * 20 + np];
            }
        }

        // produce H chunks for i0 and i1 from ONE g_Cb read pass
        {
            const int k4 = lid * 4;
            const float4 a40 = *(const float4*)(Arow0 + cc * KC + k4);
            const float4 a41 = *(const float4*)(Arow1 + cc * KC + k4);
            const float4 w4  = *(const float4*)(wlrow + cc * KC + k4);
            #pragma unroll
            for (int r = 0; r < 16; r++) {
                const int j = wid * 16 + r;
                const float d0 = sInd0[j];
                const float d1 = sInd1[j];
                const __nv_bfloat16* crow = g_Cb + (size_t)(bTT + j) * DD + cc * KC + k4;
                uint2 cu = *(const uint2*)crow;
                float2 f0 = __bfloat1622float2(*reinterpret_cast<__nv_bfloat162*>(&cu.x));
                float2 f1 = __bfloat1622float2(*reinterpret_cast<__nv_bfloat162*>(&cu.y));
                // i0
                {
                    float h0 = fmaxf(fmaf(d0, w4.x, a40.x + f0.x), 0.f);
                    float h1 = fmaxf(fmaf(d0, w4.y, a40.y + f0.y), 0.f);
                    float h2 = fmaxf(fmaf(d0, w4.z, a40.z + f1.x), 0.f);
                    float h3 = fmaxf(fmaf(d0, w4.w, a40.w + f1.y), 0.f);
                    uint32_t u0, u1;
                    asm("cvt.rn.bf16x2.f32 %0, %1, %2;" : "=r"(u0) : "f"(h1), "f"(h0));
                    asm("cvt.rn.bf16x2.f32 %0, %1, %2;" : "=r"(u1) : "f"(h3), "f"(h2));
                    asm volatile("st.shared.v2.b32 [%0], {%1, %2};"
                                 :: "r"(sH0_base + (uint32_t)(j * HSTRIDE + k4 * 2)), "r"(u0), "r"(u1) : "memory");
                }
                // i1
                {
                    float h0 = fmaxf(fmaf(d1, w4.x, a41.x + f0.x), 0.f);
                    float h1 = fmaxf(fmaf(d1, w4.y, a41.y + f0.y), 0.f);
                    float h2 = fmaxf(fmaf(d1, w4.z, a41.z + f1.x), 0.f);
                    float h3 = fmaxf(fmaf(d1, w4.w, a41.w + f1.y), 0.f);
                    uint32_t u0, u1;
                    asm("cvt.rn.bf16x2.f32 %0, %1, %2;" : "=r"(u0) : "f"(h1), "f"(h0));
                    asm("cvt.rn.bf16x2.f32 %0, %1, %2;" : "=r"(u1) : "f"(h3), "f"(h2));
                    asm volatile("st.shared.v2.b32 [%0], {%1, %2};"
                                 :: "r"(sH0_base + (uint32_t)(TT * HSTRIDE + j * HSTRIDE + k4 * 2)), "r"(u0), "r"(u1) : "memory");
                }
            }
        }
        __syncthreads();

        // MMA: 8 k-steps x 5 n-tiles x 2 i (B fragments reused)
        #pragma unroll
        for (int ks = 0; ks < 8; ks++) {
            uint32_t a00, a01, a02, a03, a10, a11, a12, a13;
            asm volatile("ldmatrix.sync.aligned.m8n8.x4.shared.b16 {%0,%1,%2,%3}, [%4];"
                : "=r"(a00), "=r"(a01), "=r"(a02), "=r"(a03)
                : "r"(aAddr0 + (uint32_t)(ks * 32)));
            asm volatile("ldmatrix.sync.aligned.m8n8.x4.shared.b16 {%0,%1,%2,%3}, [%4];"
                : "=r"(a10), "=r"(a11), "=r"(a12), "=r"(a13)
                : "r"(aAddr1 + (uint32_t)(ks * 32)));
            #pragma unroll
            for (int nt = 0; nt < 5; nt++) {
                uint32_t b0, b1v;
                uint32_t baddr = sB_base + (uint32_t)(((ks * 2 + bHalf) * 5 + nt) * 128) + bRow;
                asm volatile("ldmatrix.sync.aligned.m8n8.x2.trans.shared.b16 {%0,%1}, [%2];"
                    : "=r"(b0), "=r"(b1v) : "r"(baddr));
                asm volatile("mma.sync.aligned.m16n8k16.row.col.f32.bf16.bf16.f32 "
                    "{%0,%1,%2,%3}, {%4,%5,%6,%7}, {%8,%9}, {%0,%1,%2,%3};"
                    : "+f"(acc[0][nt][0]), "+f"(acc[0][nt][1]), "+f"(acc[0][nt][2]), "+f"(acc[0][nt][3])
                    : "r"(a00), "r"(a01), "r"(a02), "r"(a03), "r"(b0), "r"(b1v));
                asm volatile("mma.sync.aligned.m16n8k16.row.col.f32.bf16.bf16.f32 "
                    "{%0,%1,%2,%3}, {%4,%5,%6,%7}, {%8,%9}, {%0,%1,%2,%3};"
                    : "+f"(acc[1][nt][0]), "+f"(acc[1][nt][1]), "+f"(acc[1][nt][2]), "+f"(acc[1][nt][3])
                    : "r"(a10), "r"(a11), "r"(a12), "r"(a13), "r"(b0), "r"(b1v));
            }
        }
        __syncthreads();
    }

    // ---- epilogue: finalize logits, store, LSE partials ----
    float vv[2][2][10];   // [ii][half][col]
    {
        const int lcol = (lid & 3) * 2;
        const float wl768 = wlrow[768], wl769 = wlrow[769];
        #pragma unroll
        for (int ii = 0; ii < 2; ii++) {
            const float* Ar = ii ? Arow1 : Arow0;
            const float* sI = ii ? sInd1 : sInd0;
            const int iv = ii ? i1 : i0;
            const float a768 = Ar[768], a769 = Ar[769];
            #pragma unroll
            for (int half = 0; half < 2; half++) {
                const int j = wid * 16 + (lid >> 2) + half * 8;
                const float ind = sI[j];
                const float2 ct = *(const float2*)(g_Ct + (size_t)(bTT + j) * 2);
                const float h768 = fmaxf(fmaf(ind, wl768, a768 + ct.x), 0.f);
                const float h769 = fmaxf(fmaf(ind, wl769, a769 + ct.y), 0.f);
                const bool msk = span_avail[iv * TT + j] >= 1;
                float* orow = out + ((size_t)(b * PP + iv * TT + j)) * LL;
                #pragma unroll
                for (int nt = 0; nt < 5; nt++) {
                    const int col = nt * 8 + lcol;
                    float r0 = acc[ii][nt][half * 2 + 0];
                    float r1 = acc[ii][nt][half * 2 + 1];
                    float2 v;
                    v.x = msk ? (r0 + sB2[col]     + h768 * sW2a[col]     + h769 * sW2b[col])     : 0.f;
                    v.y = msk ? (r1 + sB2[col + 1] + h768 * sW2a[col + 1] + h769 * sW2b[col + 1]) : 0.f;
                    *(float2*)(orow + col) = v;
                    vv[ii][half][nt * 2 + 0] = v.x;
                    vv[ii][half][nt * 2 + 1] = v.y;
                }
            }
        }
    }
    // per-warp reduction over 16 j-rows (lane bits 2..4), per ii
    float pm[2][10], ps[2][10];
    #pragma unroll
    for (int ii = 0; ii < 2; ii++) {
        #pragma unroll
        for (int c = 0; c < 10; c++) {
            float m = fmaxf(vv[ii][0][c], vv[ii][1][c]);
            m = fmaxf(m, __shfl_xor_sync(0xffffffffu, m, 4));
            m = fmaxf(m, __shfl_xor_sync(0xffffffffu, m, 8));
            m = fmaxf(m, __shfl_xor_sync(0xffffffffu, m, 16));
            float s = __expf(vv[ii][0][c] - m) + __expf(vv[ii][1][c] - m);
            s += __shfl_xor_sync(0xffffffffu, s, 4);
            s += __shfl_xor_sync(0xffffffffu, s, 8);
            s += __shfl_xor_sync(0xffffffffu, s, 16);
            pm[ii][c] = m; ps[ii][c] = s;
        }
    }
    // cross-warp merge via smem (reuse sB region; safe: last loop iter ended in __syncthreads)
    float* sRm = (float*)sB;            // [2][8][40]
    float* sRs = sRm + 2 * 8 * LL;      // [2][8][40]
    if (lid < 4) {
        const int lcol = lid * 2;
        #pragma unroll
        for (int ii = 0; ii < 2; ii++) {
            #pragma unroll
            for (int nt = 0; nt < 5; nt++) {
                sRm[(ii * 8 + wid) * LL + nt * 8 + lcol]     = pm[ii][nt * 2 + 0];
                sRm[(ii * 8 + wid) * LL + nt * 8 + lcol + 1] = pm[ii][nt * 2 + 1];
                sRs[(ii * 8 + wid) * LL + nt * 8 + lcol]     = ps[ii][nt * 2 + 0];
                sRs[(ii * 8 + wid) * LL + nt * 8 + lcol + 1] = ps[ii][nt * 2 + 1];
            }
        }
    }
    __syncthreads();
    if (tid < 2 * LL) {
        const int ii = tid / LL, l = tid % LL;
        const int iv = ii ? i1 : i0;
        float m = sRm[ii * 8 * LL + l];
        #pragma unroll
        for (int w = 1; w < 8; w++) m = fmaxf(m, sRm[(ii * 8 + w) * LL + l]);
        float s = 0.f;
        #pragma unroll
        for (int w = 0; w < 8; w++) s += sRs[(ii * 8 + w) * LL + l] * __expf(sRm[(ii * 8 + w) * LL + l] - m);
        g_M[(bTT + iv) * LL + l] = m;
        g_S[(bTT + iv) * LL + l] = s;
    }
}

// ---------------------------------------------------------------------------
// Kernel 3: combine 128 partials per (b,l) -> g_LSE.  grid (40,4), 128 thr
// ---------------------------------------------------------------------------
__global__ void lse_combine_kernel()
{
    const int l = blockIdx.x, b = blockIdx.y;
    const int t = threadIdx.x;
    float m = g_M[(b * TT + t) * LL + l];
    float s = g_S[(b * TT + t) * LL + l];
    #pragma unroll
    for (int off = 16; off > 0; off >>= 1) {
        float m2 = __shfl_xor_sync(0xffffffffu, m, off);
        float s2 = __shfl_xor_sync(0xffffffffu, s, off);
        float mn = fmaxf(m, m2);
        s = s * __expf(m - mn) + s2 * __expf(m2 - mn);
        m = mn;
    }
    __shared__ float sm[4], ss[4];
    if ((t & 31) == 0) { sm[t >> 5] = m; ss[t >> 5] = s; }
    __syncthreads();
    if (t == 0) {
        m = sm[0]; s = ss[0];
        #pragma unroll
        for (int w = 1; w < 4; w++) {
            float mn = fmaxf(m, sm[w]);
            s = s * __expf(m - mn) + ss[w] * __expf(sm[w] - mn);
            m = mn;
        }
        g_LSE[b * LL + l] = m + logf(s);
    }
}

// ---------------------------------------------------------------------------
// Kernel 4: out -= lse (float4).  grid 2560, block 256
// ---------------------------------------------------------------------------
__global__ void sub_lse_kernel(float* __restrict__ out)
{
    int e = blockIdx.x * 256 + threadIdx.x;       // 0..655359 float4s
    int b = e / (PP * LL / 4);
    int r = e % (PP * LL / 4);
    int l0 = (r * 4) % LL;
    float4 lv = *(const float4*)(g_LSE + b * LL + l0);
    float4 v = ((const float4*)out)[e];
    v.x -= lv.x; v.y -= lv.y; v.z -= lv.z; v.w -= lv.w;
    ((float4*)out)[e] = v;
}

// ---------------------------------------------------------------------------
extern "C" void kernel_launch(void* const* d_in, const int* in_sizes, int n_in,
                              void* d_out, int out_size)
{
    const float* hidden     = (const float*)d_in[0];
    const float* W1         = (const float*)d_in[1];
    const float* b1         = (const float*)d_in[2];
    const float* W2         = (const float*)d_in[3];
    const float* b2         = (const float*)d_in[4];
    const int*   pred_spans = (const int*)d_in[5];
    const int*   span_avail = (const int*)d_in[6];
    float* out = (float*)d_out;

    cudaFuncSetAttribute(pair_mma_kernel, cudaFuncAttributeMaxDynamicSharedMemorySize, DYN_BYTES);

    w2b_prep_kernel<<<(DD * LL + 255) / 256, 256>>>(W2);
    gemm_w1_tf32_kernel<<<dim3(13, 4, 2), 256>>>(hidden, W1, b1);
    pair_mma_kernel<<<NROWS / 2, 256, DYN_BYTES>>>(W1, W2, b2, pred_spans, span_avail, out);
    lse_combine_kernel<<<dim3(LL, BB), 128>>>();
    sub_lse_kernel<<<(BB * PP * LL / 4) / 256, 256>>>(out);
}